// round 1
// baseline (speedup 1.0000x reference)
#include <cuda_runtime.h>

// Problem constants (fixed by setup_inputs)
#define BATCH 4
#define N_UP  8192
#define N_GT  8192
#define N_RAD 1024
#define CHUNK 512          // b-points per block tile
#define NTHREADS 256

// Scratch: per-point running min of squared distance (float bits, nonneg -> int order == float order)
__device__ int g_min1[BATCH * N_UP];   // up -> gt
__device__ int g_min2[BATCH * N_GT];   // gt -> up
__device__ int g_min3[BATCH * N_RAD];  // radar -> gt

typedef unsigned long long ull;

__device__ __forceinline__ ull fma2(ull a, ull b, ull c) {
    ull d;
    asm("fma.rn.f32x2 %0, %1, %2, %3;" : "=l"(d) : "l"(a), "l"(b), "l"(c));
    return d;
}
__device__ __forceinline__ ull pack2(float lo, float hi) {
    ull d;
    asm("mov.b64 %0, {%1, %2};" : "=l"(d)
        : "r"(__float_as_uint(lo)), "r"(__float_as_uint(hi)));
    return d;
}
__device__ __forceinline__ float2 unpack2(ull v) {
    unsigned lo, hi;
    asm("mov.b64 {%0, %1}, %2;" : "=r"(lo), "=r"(hi) : "l"(v));
    return make_float2(__uint_as_float(lo), __uint_as_float(hi));
}

// One block: APT*NTHREADS a-points vs CHUNK b-points.
// min_j (a^2 + b^2 - 2 a.b) = a^2 - 2 * max_j (a.b - 0.5*b^2)
template <int APT>
__device__ __forceinline__ void pair_pass(
    ulonglong2* tile,
    const float* __restrict__ apts,   // flat [Btot*3], a_start indexes globally
    const float* __restrict__ bpts,   // already offset to this batch
    int* __restrict__ gout,
    int a_start, int b_start)
{
    const int tid = threadIdx.x;

    // Load b tile, duplicated pairs: [2k] = ({bx,bx},{by,by}), [2k+1] = ({bz,bz},{n,n})
    for (int i = tid; i < CHUNK; i += NTHREADS) {
        const float* p = bpts + 3 * (b_start + i);
        float x = p[0], y = p[1], z = p[2];
        float nb2 = -0.5f * (x * x + y * y + z * z);
        tile[2 * i]     = make_ulonglong2(pack2(x, x), pack2(y, y));
        tile[2 * i + 1] = make_ulonglong2(pack2(z, z), pack2(nb2, nb2));
    }
    __syncthreads();

    constexpr int NP = APT / 2;
    ull AX[NP], AY[NP], AZ[NP];
    float a2[APT], smax[APT];

#pragma unroll
    for (int p = 0; p < NP; ++p) {
        int i0 = a_start + tid + (2 * p) * NTHREADS;
        int i1 = a_start + tid + (2 * p + 1) * NTHREADS;
        const float* q0 = apts + 3 * i0;
        const float* q1 = apts + 3 * i1;
        float x0 = q0[0], y0 = q0[1], z0 = q0[2];
        float x1 = q1[0], y1 = q1[1], z1 = q1[2];
        AX[p] = pack2(x0, x1);
        AY[p] = pack2(y0, y1);
        AZ[p] = pack2(z0, z1);
        a2[2 * p]     = x0 * x0 + y0 * y0 + z0 * z0;
        a2[2 * p + 1] = x1 * x1 + y1 * y1 + z1 * z1;
        smax[2 * p]     = -3.0e38f;
        smax[2 * p + 1] = -3.0e38f;
    }

#pragma unroll 4
    for (int k = 0; k < CHUNK; ++k) {
        ulonglong2 p0 = tile[2 * k];       // {bx,bx},{by,by}
        ulonglong2 p1 = tile[2 * k + 1];   // {bz,bz},{nb2,nb2}
#pragma unroll
        for (int p = 0; p < NP; ++p) {
            ull acc = fma2(AZ[p], p1.x, p1.y);   // az*bz + nb2
            acc     = fma2(AY[p], p0.y, acc);
            acc     = fma2(AX[p], p0.x, acc);
            float2 s = unpack2(acc);
            smax[2 * p]     = fmaxf(smax[2 * p], s.x);
            smax[2 * p + 1] = fmaxf(smax[2 * p + 1], s.y);
        }
    }

#pragma unroll
    for (int j = 0; j < APT; ++j) {
        int idx = a_start + tid + j * NTHREADS;
        float d = fmaxf(fmaf(-2.0f, smax[j], a2[j]), 0.0f);  // clamp like reference
        atomicMin(gout + idx, __float_as_int(d));
    }
}

// Role-decoded pairs kernel.
// blocks [0,256):    pass1 up->gt   (16 a-blocks of 2048) x (16 gt chunks)
// blocks [256,512):  pass2 gt->up   (16 a-blocks of 2048) x (16 up chunks)
// blocks [512,576):  radar->gt      ( 4 a-blocks of 1024) x (16 gt chunks)
__global__ void __launch_bounds__(NTHREADS)
pairs_kernel(const float* __restrict__ pc_up,
             const float* __restrict__ pc2,
             const float* __restrict__ pc3)
{
    __shared__ ulonglong2 tile[CHUNK * 2];
    int bid = blockIdx.x;
    if (bid < 256) {
        int ablk = bid >> 4, g = bid & 15;
        int a_start = ablk * (8 * NTHREADS);     // 2048
        int batch = a_start >> 13;               // / 8192
        pair_pass<8>(tile, pc_up, pc2 + batch * N_GT * 3, g_min1, a_start, g * CHUNK);
    } else if (bid < 512) {
        int r = bid - 256;
        int ablk = r >> 4, g = r & 15;
        int a_start = ablk * (8 * NTHREADS);
        int batch = a_start >> 13;
        pair_pass<8>(tile, pc2, pc_up + batch * N_UP * 3, g_min2, a_start, g * CHUNK);
    } else {
        int r = bid - 512;
        int ablk = r >> 4, g = r & 15;
        int a_start = ablk * (4 * NTHREADS);     // 1024 = one batch of radar points
        int batch = ablk;
        pair_pass<4>(tile, pc3, pc2 + batch * N_GT * 3, g_min3, a_start, g * CHUNK);
    }
}

__global__ void init_kernel() {
    int i = blockIdx.x * blockDim.x + threadIdx.x;
    const int T1 = BATCH * N_UP;
    const int T2 = T1 + BATCH * N_GT;
    const int T3 = T2 + BATCH * N_RAD;
    if (i < T1)      g_min1[i] = 0x7f7fffff;           // FLT_MAX bits
    else if (i < T2) g_min2[i - T1] = 0x7f7fffff;
    else if (i < T3) g_min3[i - T2] = 0x7f7fffff;
}

// Deterministic final reduction: fixed per-thread strided partials + smem tree.
__global__ void __launch_bounds__(1024)
reduce_kernel(const float* __restrict__ conf, float* __restrict__ out)
{
    int tid = threadIdx.x;
    float s_d1 = 0.f, s_sqrt1 = 0.f, s_d2 = 0.f, s_conf = 0.f;

    for (int i = tid; i < BATCH * N_UP; i += 1024) {
        float d = __int_as_float(g_min1[i]);
        s_d1 += d;
        s_sqrt1 += sqrtf(d);
    }
    for (int i = tid; i < BATCH * N_GT; i += 1024)
        s_d2 += __int_as_float(g_min2[i]);
    for (int i = tid; i < BATCH * N_RAD; i += 1024) {
        float d = __int_as_float(g_min3[i]);
        float gs = expf(-sqrtf(d));
        float diff = conf[i] - gs;
        s_conf += diff * diff;
    }

    __shared__ float r1[1024], r2[1024], r3[1024], r4[1024];
    r1[tid] = s_d1; r2[tid] = s_sqrt1; r3[tid] = s_d2; r4[tid] = s_conf;
    __syncthreads();
    for (int s = 512; s > 0; s >>= 1) {
        if (tid < s) {
            r1[tid] += r1[tid + s];
            r2[tid] += r2[tid + s];
            r3[tid] += r3[tid + s];
            r4[tid] += r4[tid + s];
        }
        __syncthreads();
    }
    if (tid == 0) {
        const float inv_up  = 1.0f / (BATCH * N_UP);
        const float inv_gt  = 1.0f / (BATCH * N_GT);
        const float inv_rad = 1.0f / (BATCH * N_RAD);
        float mean1     = r1[0] * inv_up;    // mean(dist1)
        float mean_sqrt = r2[0] * inv_up;    // mean(sqrt(dist1)) = emd
        float mean2     = r3[0] * inv_gt;    // mean(dist2)
        float conf_loss = r4[0] * inv_rad;
        float chamfer = 0.5f * mean1 + 2.0f * mean2;
        out[0] = 0.5f * chamfer + 0.5f * conf_loss + mean_sqrt;  // ALPHA = 0.5
    }
}

extern "C" void kernel_launch(void* const* d_in, const int* in_sizes, int n_in,
                              void* d_out, int out_size)
{
    (void)in_sizes; (void)n_in; (void)out_size;
    const float* pc_up   = (const float*)d_in[0];
    // d_in[1] = pc_seed (unused by the reference loss)
    const float* pc_conf = (const float*)d_in[2];
    const float* pc2     = (const float*)d_in[3];
    const float* pc3     = (const float*)d_in[4];

    const int total_mins = BATCH * (N_UP + N_GT + N_RAD);
    init_kernel<<<(total_mins + 255) / 256, 256>>>();
    pairs_kernel<<<576, NTHREADS>>>(pc_up, pc2, pc3);
    reduce_kernel<<<1, 1024>>>(pc_conf, (float*)d_out);
}

// round 3
// speedup vs baseline: 1.2322x; 1.2322x over previous
#include <cuda_runtime.h>

// Problem constants (fixed by setup_inputs)
#define BATCH 4
#define N_UP  8192
#define N_GT  8192
#define N_RAD 1024
#define RCHUNK 512         // radar pass: b-points per block tile
#define NTHREADS 256

// Scratch: per-point running min of squared distance (float bits; nonneg -> int order == float order)
__device__ int g_min1[BATCH * N_UP];   // up -> gt
__device__ int g_min2[BATCH * N_GT];   // gt -> up
__device__ int g_min3[BATCH * N_RAD];  // radar -> gt

typedef unsigned long long ull;

__device__ __forceinline__ ull fma2(ull a, ull b, ull c) {
    ull d;
    asm("fma.rn.f32x2 %0, %1, %2, %3;" : "=l"(d) : "l"(a), "l"(b), "l"(c));
    return d;
}
__device__ __forceinline__ ull add2(ull a, ull b) {
    ull d;
    asm("add.rn.f32x2 %0, %1, %2;" : "=l"(d) : "l"(a), "l"(b));
    return d;
}
__device__ __forceinline__ ull pack2(float lo, float hi) {
    ull d;
    asm("mov.b64 %0, {%1, %2};" : "=l"(d)
        : "r"(__float_as_uint(lo)), "r"(__float_as_uint(hi)));
    return d;
}
__device__ __forceinline__ float2 unpack2(ull v) {
    unsigned lo, hi;
    asm("mov.b64 {%0, %1}, %2;" : "=r"(lo), "=r"(hi) : "l"(v));
    return make_float2(__uint_as_float(lo), __uint_as_float(hi));
}

// ---------------- shared memory (union: fused chamfer vs radar path) --------
struct SmemFused {
    ull   sb[128 * 4];      // 4KB: dup-packed b tile: per b {x,x},{y,y},{z,z},{nb,nb}
    float red[128 * 17];    // 8.5KB: padded reduce array (col per chunk, row at end)
};
struct SmemRadar {
    ulonglong2 tile[RCHUNK * 2];  // 16KB
};
union SmemAll { SmemFused f; SmemRadar r; };

// ---------------- radar pass (unfused, round-1 machinery, APT=4) ------------
// min_j (a^2 + b^2 - 2 a.b) = a^2 - 2 * max_j (a.b - 0.5*b^2)
__device__ __forceinline__ void radar_pass(
    ulonglong2* tile,
    const float* __restrict__ apts,   // flat, a_start global
    const float* __restrict__ bpts,   // offset to batch
    int* __restrict__ gout,
    int a_start, int b_start)
{
    const int tid = threadIdx.x;

    for (int i = tid; i < RCHUNK; i += NTHREADS) {
        const float* p = bpts + 3 * (b_start + i);
        float x = p[0], y = p[1], z = p[2];
        float nb2 = -0.5f * (x * x + y * y + z * z);
        tile[2 * i]     = make_ulonglong2(pack2(x, x), pack2(y, y));
        tile[2 * i + 1] = make_ulonglong2(pack2(z, z), pack2(nb2, nb2));
    }
    __syncthreads();

    ull AX[2], AY[2], AZ[2];
    float a2[4], smax[4];
#pragma unroll
    for (int p = 0; p < 2; ++p) {
        int i0 = a_start + tid + (2 * p) * NTHREADS;
        int i1 = a_start + tid + (2 * p + 1) * NTHREADS;
        const float* q0 = apts + 3 * i0;
        const float* q1 = apts + 3 * i1;
        float x0 = q0[0], y0 = q0[1], z0 = q0[2];
        float x1 = q1[0], y1 = q1[1], z1 = q1[2];
        AX[p] = pack2(x0, x1); AY[p] = pack2(y0, y1); AZ[p] = pack2(z0, z1);
        a2[2 * p]     = x0 * x0 + y0 * y0 + z0 * z0;
        a2[2 * p + 1] = x1 * x1 + y1 * y1 + z1 * z1;
        smax[2 * p] = smax[2 * p + 1] = -3.0e38f;
    }

#pragma unroll 4
    for (int k = 0; k < RCHUNK; ++k) {
        ulonglong2 p0 = tile[2 * k];
        ulonglong2 p1 = tile[2 * k + 1];
#pragma unroll
        for (int p = 0; p < 2; ++p) {
            ull acc = fma2(AZ[p], p1.x, p1.y);
            acc     = fma2(AY[p], p0.y, acc);
            acc     = fma2(AX[p], p0.x, acc);
            float2 s = unpack2(acc);
            smax[2 * p]     = fmaxf(smax[2 * p], s.x);
            smax[2 * p + 1] = fmaxf(smax[2 * p + 1], s.y);
        }
    }

#pragma unroll
    for (int j = 0; j < 4; ++j) {
        int idx = a_start + tid + j * NTHREADS;
        float d = fmaxf(fmaf(-2.0f, smax[j], a2[j]), 0.0f);
        atomicMin(gout + idx, __float_as_int(d));
    }
}

// ---------------- pairs kernel ----------------------------------------------
// blocks [0,512):   fused chamfer up<->gt. Block = (batch, ablk of 128 up, bhalf).
//                   Loops 32 chunks of 128 gt (= its 4096-gt half).
// blocks [512,576): radar -> gt, unfused.
__global__ void __launch_bounds__(NTHREADS)
pairs_kernel(const float* __restrict__ pc_up,
             const float* __restrict__ pc2,
             const float* __restrict__ pc3)
{
    __shared__ SmemAll sm;
    const int tid = threadIdx.x;
    const int bid = blockIdx.x;

    if (bid < 512) {
        const int batch = bid >> 7;
        const int r2    = bid & 127;
        const int ablk  = r2 >> 1;
        const int bhalf = r2 & 1;
        const float* Ap = pc_up + (batch * N_UP + ablk * 128) * 3;
        const float* Bp = pc2   + (batch * N_GT + bhalf * 4096) * 3;
        const int ta = tid & 15;   // a-group (8 a-points each)
        const int tb = tid >> 4;   // b-group (8 b-points each)

        // Thread's 8 a-points as 4 packed pairs; symmetric score needs -a^2/2.
        ull AX[4], AY[4], AZ[4], NA[4];
        float rowmax[8];
#pragma unroll
        for (int p = 0; p < 4; ++p) {
            const float* q0 = Ap + 3 * (ta * 8 + 2 * p);
            float x0 = q0[0], y0 = q0[1], z0 = q0[2];
            float x1 = q0[3], y1 = q0[4], z1 = q0[5];
            AX[p] = pack2(x0, x1); AY[p] = pack2(y0, y1); AZ[p] = pack2(z0, z1);
            NA[p] = pack2(-0.5f * (x0 * x0 + y0 * y0 + z0 * z0),
                          -0.5f * (x1 * x1 + y1 * y1 + z1 * z1));
            rowmax[2 * p] = rowmax[2 * p + 1] = -3.0e38f;
        }

        for (int chunk = 0; chunk < 32; ++chunk) {
            __syncthreads();   // previous iteration's sb/red reads complete
            if (tid < 128) {
                const float* p = Bp + 3 * (chunk * 128 + tid);
                float x = p[0], y = p[1], z = p[2];
                float nb = -0.5f * (x * x + y * y + z * z);
                ull* d = &sm.f.sb[tid * 4];
                d[0] = pack2(x, x); d[1] = pack2(y, y);
                d[2] = pack2(z, z); d[3] = pack2(nb, nb);
            }
            __syncthreads();

            float colmax[8];
#pragma unroll
            for (int j = 0; j < 8; ++j) colmax[j] = -3.0e38f;

#pragma unroll
            for (int j = 0; j < 8; ++j) {
                const ull* bb = &sm.f.sb[(tb * 8 + j) * 4];
                ull bx = bb[0], by = bb[1], bz = bb[2], nb = bb[3];
#pragma unroll
                for (int p = 0; p < 4; ++p) {
                    ull acc = fma2(AZ[p], bz, nb);
                    acc     = fma2(AY[p], by, acc);
                    acc     = fma2(AX[p], bx, acc);
                    ull s   = add2(acc, NA[p]);          // s = a.b - a^2/2 - b^2/2 = -d/2
                    float2 f = unpack2(s);
                    rowmax[2 * p]     = fmaxf(rowmax[2 * p],     f.x);
                    rowmax[2 * p + 1] = fmaxf(rowmax[2 * p + 1], f.y);
                    colmax[j] = fmaxf(colmax[j], f.x);
                    colmax[j] = fmaxf(colmax[j], f.y);
                }
            }

            // column (gt->up) partial reduce across the 16 ta-groups
#pragma unroll
            for (int j = 0; j < 8; ++j)
                sm.f.red[(tb * 8 + j) * 17 + ta] = colmax[j];
            __syncthreads();
            if (tid < 128) {
                const float* row = &sm.f.red[tid * 17];
                float m = row[0];
#pragma unroll
                for (int i = 1; i < 16; ++i) m = fmaxf(m, row[i]);
                float d = fmaxf(-2.0f * m, 0.0f);
                atomicMin(g_min2 + batch * N_GT + bhalf * 4096 + chunk * 128 + tid,
                          __float_as_int(d));
            }
        }

        // row (up->gt) reduce across the 16 tb-groups
        __syncthreads();
#pragma unroll
        for (int j = 0; j < 8; ++j)
            sm.f.red[(ta * 8 + j) * 17 + tb] = rowmax[j];
        __syncthreads();
        if (tid < 128) {
            const float* row = &sm.f.red[tid * 17];
            float m = row[0];
#pragma unroll
            for (int i = 1; i < 16; ++i) m = fmaxf(m, row[i]);
            float d = fmaxf(-2.0f * m, 0.0f);
            atomicMin(g_min1 + batch * N_UP + ablk * 128 + tid, __float_as_int(d));
        }
    } else {
        // radar -> gt
        const int r = bid - 512;
        const int batch = r >> 4;
        const int g = r & 15;
        radar_pass(sm.r.tile, pc3, pc2 + batch * N_GT * 3, g_min3,
                   batch * N_RAD, g * RCHUNK);
    }
}

// ---------------- init ------------------------------------------------------
__global__ void init_kernel() {
    const int T1 = BATCH * N_UP;   // 32768
    const int T2 = BATCH * N_GT;   // 32768
    const int T3 = BATCH * N_RAD;  // 4096
    int i = blockIdx.x * blockDim.x + threadIdx.x;   // int4 index
    const int4 v = make_int4(0x7f7fffff, 0x7f7fffff, 0x7f7fffff, 0x7f7fffff);
    int n1 = T1 / 4, n2 = T2 / 4, n3 = T3 / 4;
    if (i < n1)                ((int4*)g_min1)[i] = v;
    else if (i < n1 + n2)      ((int4*)g_min2)[i - n1] = v;
    else if (i < n1 + n2 + n3) ((int4*)g_min3)[i - n1 - n2] = v;
}

// ---------------- final reduction (deterministic) ---------------------------
__global__ void __launch_bounds__(1024)
reduce_kernel(const float* __restrict__ conf, float* __restrict__ out)
{
    int tid = threadIdx.x;
    float s_d1 = 0.f, s_sqrt1 = 0.f, s_d2 = 0.f, s_conf = 0.f;

    for (int i = tid; i < BATCH * N_UP; i += 1024) {
        float d = __int_as_float(g_min1[i]);
        s_d1 += d;
        s_sqrt1 += sqrtf(d);
    }
    for (int i = tid; i < BATCH * N_GT; i += 1024)
        s_d2 += __int_as_float(g_min2[i]);
    for (int i = tid; i < BATCH * N_RAD; i += 1024) {
        float d = __int_as_float(g_min3[i]);
        float gs = expf(-sqrtf(d));
        float diff = conf[i] - gs;
        s_conf += diff * diff;
    }

    __shared__ float r1[1024], r2[1024], r3[1024], r4[1024];
    r1[tid] = s_d1; r2[tid] = s_sqrt1; r3[tid] = s_d2; r4[tid] = s_conf;
    __syncthreads();
    for (int s = 512; s > 0; s >>= 1) {
        if (tid < s) {
            r1[tid] += r1[tid + s];
            r2[tid] += r2[tid + s];
            r3[tid] += r3[tid + s];
            r4[tid] += r4[tid + s];
        }
        __syncthreads();
    }
    if (tid == 0) {
        const float inv_up  = 1.0f / (BATCH * N_UP);
        const float inv_gt  = 1.0f / (BATCH * N_GT);
        const float inv_rad = 1.0f / (BATCH * N_RAD);
        float mean1     = r1[0] * inv_up;
        float mean_sqrt = r2[0] * inv_up;
        float mean2     = r3[0] * inv_gt;
        float conf_loss = r4[0] * inv_rad;
        float chamfer = 0.5f * mean1 + 2.0f * mean2;
        out[0] = 0.5f * chamfer + 0.5f * conf_loss + mean_sqrt;  // ALPHA = 0.5
    }
}

extern "C" void kernel_launch(void* const* d_in, const int* in_sizes, int n_in,
                              void* d_out, int out_size)
{
    (void)in_sizes; (void)n_in; (void)out_size;
    const float* pc_up   = (const float*)d_in[0];
    // d_in[1] = pc_seed (unused by the reference loss)
    const float* pc_conf = (const float*)d_in[2];
    const float* pc2     = (const float*)d_in[3];
    const float* pc3     = (const float*)d_in[4];

    const int total_vec4 = (BATCH * (N_UP + N_GT + N_RAD)) / 4;  // 17408
    init_kernel<<<(total_vec4 + 255) / 256, 256>>>();
    pairs_kernel<<<576, NTHREADS>>>(pc_up, pc2, pc3);
    reduce_kernel<<<1, 1024>>>(pc_conf, (float*)d_out);
}

// round 4
// speedup vs baseline: 1.3571x; 1.1013x over previous
#include <cuda_runtime.h>

// Problem constants (fixed by setup_inputs)
#define BATCH 4
#define N_UP  8192
#define N_GT  8192
#define N_RAD 1024
#define RCHUNK 512         // radar pass: b-points per block tile
#define NTHREADS 256

// Scratch: per-point running min of squared distance (float bits; nonneg -> int order == float order)
__device__ int g_min1[BATCH * N_UP];   // up -> gt
__device__ int g_min2[BATCH * N_GT];   // gt -> up
__device__ int g_min3[BATCH * N_RAD];  // radar -> gt

typedef unsigned long long ull;

__device__ __forceinline__ ull fma2(ull a, ull b, ull c) {
    ull d;
    asm("fma.rn.f32x2 %0, %1, %2, %3;" : "=l"(d) : "l"(a), "l"(b), "l"(c));
    return d;
}
__device__ __forceinline__ ull add2(ull a, ull b) {
    ull d;
    asm("add.rn.f32x2 %0, %1, %2;" : "=l"(d) : "l"(a), "l"(b));
    return d;
}
__device__ __forceinline__ ull pack2(float lo, float hi) {
    ull d;
    asm("mov.b64 %0, {%1, %2};" : "=l"(d)
        : "r"(__float_as_uint(lo)), "r"(__float_as_uint(hi)));
    return d;
}
__device__ __forceinline__ float2 unpack2(ull v) {
    unsigned lo, hi;
    asm("mov.b64 {%0, %1}, %2;" : "=r"(lo), "=r"(hi) : "l"(v));
    return make_float2(__uint_as_float(lo), __uint_as_float(hi));
}

// ---------------- shared memory (union: fused chamfer vs radar path) --------
struct SmemFused {
    ull   sb[128 * 4];      // 4KB: dup-packed b tile: per b {x,x},{y,y},{z,z},{nb,nb}
    float red[128 * 17];    // 8.5KB: padded reduce array
};
struct SmemRadar {
    ulonglong2 tile[RCHUNK * 2];  // 16KB
};
union SmemAll { SmemFused f; SmemRadar r; };

// ---------------- radar pass (unfused, APT=4) -------------------------------
// min_j (a^2 + b^2 - 2 a.b) = a^2 - 2 * max_j (a.b - 0.5*b^2)
__device__ __forceinline__ void radar_pass(
    ulonglong2* tile,
    const float* __restrict__ apts,
    const float* __restrict__ bpts,
    int* __restrict__ gout,
    int a_start, int b_start)
{
    const int tid = threadIdx.x;

    for (int i = tid; i < RCHUNK; i += NTHREADS) {
        const float* p = bpts + 3 * (b_start + i);
        float x = p[0], y = p[1], z = p[2];
        float nb2 = -0.5f * (x * x + y * y + z * z);
        tile[2 * i]     = make_ulonglong2(pack2(x, x), pack2(y, y));
        tile[2 * i + 1] = make_ulonglong2(pack2(z, z), pack2(nb2, nb2));
    }
    __syncthreads();

    ull AX[2], AY[2], AZ[2];
    float a2[4], smax[4];
#pragma unroll
    for (int p = 0; p < 2; ++p) {
        int i0 = a_start + tid + (2 * p) * NTHREADS;
        int i1 = a_start + tid + (2 * p + 1) * NTHREADS;
        const float* q0 = apts + 3 * i0;
        const float* q1 = apts + 3 * i1;
        float x0 = q0[0], y0 = q0[1], z0 = q0[2];
        float x1 = q1[0], y1 = q1[1], z1 = q1[2];
        AX[p] = pack2(x0, x1); AY[p] = pack2(y0, y1); AZ[p] = pack2(z0, z1);
        a2[2 * p]     = x0 * x0 + y0 * y0 + z0 * z0;
        a2[2 * p + 1] = x1 * x1 + y1 * y1 + z1 * z1;
        smax[2 * p] = smax[2 * p + 1] = -3.0e38f;
    }

#pragma unroll 4
    for (int k = 0; k < RCHUNK; ++k) {
        ulonglong2 p0 = tile[2 * k];
        ulonglong2 p1 = tile[2 * k + 1];
#pragma unroll
        for (int p = 0; p < 2; ++p) {
            ull acc = fma2(AZ[p], p1.x, p1.y);
            acc     = fma2(AY[p], p0.y, acc);
            acc     = fma2(AX[p], p0.x, acc);
            float2 s = unpack2(acc);
            smax[2 * p]     = fmaxf(smax[2 * p], s.x);
            smax[2 * p + 1] = fmaxf(smax[2 * p + 1], s.y);
        }
    }

#pragma unroll
    for (int j = 0; j < 4; ++j) {
        int idx = a_start + tid + j * NTHREADS;
        float d = fmaxf(fmaf(-2.0f, smax[j], a2[j]), 0.0f);
        atomicMin(gout + idx, __float_as_int(d));
    }
}

// ---------------- b-tile loader (one point per thread in upper half) --------
__device__ __forceinline__ void load_b_point(ull* sb, const float* __restrict__ Bp,
                                             int chunk, int slot)
{
    const float* p = Bp + 3 * (chunk * 128 + slot);
    float x = p[0], y = p[1], z = p[2];
    float nb = -0.5f * (x * x + y * y + z * z);
    ull* d = &sb[slot * 4];
    d[0] = pack2(x, x); d[1] = pack2(y, y);
    d[2] = pack2(z, z); d[3] = pack2(nb, nb);
}

// ---------------- pairs kernel ----------------------------------------------
// blocks [0,512):   fused chamfer up<->gt. Block = (batch, ablk of 128 up, bhalf).
//                   Loops 32 chunks of 128 gt (= its 4096-gt half).
//                   Per chunk: 2 syncs; col-reduce (low 128 thr) overlapped
//                   with next-chunk b load (high 128 thr).
// blocks [512,576): radar -> gt, unfused.
__global__ void __launch_bounds__(NTHREADS)
pairs_kernel(const float* __restrict__ pc_up,
             const float* __restrict__ pc2,
             const float* __restrict__ pc3)
{
    __shared__ SmemAll sm;
    const int tid = threadIdx.x;
    const int bid = blockIdx.x;

    if (bid < 512) {
        const int batch = bid >> 7;
        const int r2    = bid & 127;
        const int ablk  = r2 >> 1;
        const int bhalf = r2 & 1;
        const float* Ap = pc_up + (batch * N_UP + ablk * 128) * 3;
        const float* Bp = pc2   + (batch * N_GT + bhalf * 4096) * 3;
        const int ta = tid & 15;   // a-group (8 a-points each)
        const int tb = tid >> 4;   // b-group (8 b-points each)

        // Thread's 8 a-points as 4 packed pairs; symmetric score needs -a^2/2.
        ull AX[4], AY[4], AZ[4], NA[4];
        float rowmax[8];
#pragma unroll
        for (int p = 0; p < 4; ++p) {
            const float* q0 = Ap + 3 * (ta * 8 + 2 * p);
            float x0 = q0[0], y0 = q0[1], z0 = q0[2];
            float x1 = q0[3], y1 = q0[4], z1 = q0[5];
            AX[p] = pack2(x0, x1); AY[p] = pack2(y0, y1); AZ[p] = pack2(z0, z1);
            NA[p] = pack2(-0.5f * (x0 * x0 + y0 * y0 + z0 * z0),
                          -0.5f * (x1 * x1 + y1 * y1 + z1 * z1));
            rowmax[2 * p] = rowmax[2 * p + 1] = -3.0e38f;
        }

        // Preload chunk 0 (upper half threads)
        if (tid >= 128) load_b_point(sm.f.sb, Bp, 0, tid - 128);
        __syncthreads();

        for (int chunk = 0; chunk < 32; ++chunk) {
            float colmax[8];
#pragma unroll
            for (int j = 0; j < 8; ++j) colmax[j] = -3.0e38f;

#pragma unroll
            for (int j = 0; j < 8; ++j) {
                const ull* bb = &sm.f.sb[(tb * 8 + j) * 4];
                ull bx = bb[0], by = bb[1], bz = bb[2], nb = bb[3];
#pragma unroll
                for (int p = 0; p < 4; ++p) {
                    ull acc = fma2(AZ[p], bz, nb);
                    acc     = fma2(AY[p], by, acc);
                    acc     = fma2(AX[p], bx, acc);
                    ull s   = add2(acc, NA[p]);          // s = a.b - a^2/2 - b^2/2 = -d/2
                    float2 f = unpack2(s);
                    rowmax[2 * p]     = fmaxf(rowmax[2 * p],     f.x);
                    rowmax[2 * p + 1] = fmaxf(rowmax[2 * p + 1], f.y);
                    colmax[j] = fmaxf(colmax[j], f.x);
                    colmax[j] = fmaxf(colmax[j], f.y);
                }
            }

            // column (gt->up) partials across the 16 ta-groups
#pragma unroll
            for (int j = 0; j < 8; ++j)
                sm.f.red[(tb * 8 + j) * 17 + ta] = colmax[j];
            __syncthreads();   // red visible; sb reads of this chunk done

            if (tid < 128) {
                // col reduce + global atomic (low half)
                const float* row = &sm.f.red[tid * 17];
                float m = row[0];
#pragma unroll
                for (int i = 1; i < 16; ++i) m = fmaxf(m, row[i]);
                float d = fmaxf(-2.0f * m, 0.0f);
                atomicMin(g_min2 + batch * N_GT + bhalf * 4096 + chunk * 128 + tid,
                          __float_as_int(d));
            } else if (chunk + 1 < 32) {
                // load next b tile (high half) — disjoint smem region
                load_b_point(sm.f.sb, Bp, chunk + 1, tid - 128);
            }
            __syncthreads();   // sb(next) visible; red reads done
        }

        // row (up->gt) reduce across the 16 tb-groups
#pragma unroll
        for (int j = 0; j < 8; ++j)
            sm.f.red[(ta * 8 + j) * 17 + tb] = rowmax[j];
        __syncthreads();
        if (tid < 128) {
            const float* row = &sm.f.red[tid * 17];
            float m = row[0];
#pragma unroll
            for (int i = 1; i < 16; ++i) m = fmaxf(m, row[i]);
            float d = fmaxf(-2.0f * m, 0.0f);
            atomicMin(g_min1 + batch * N_UP + ablk * 128 + tid, __float_as_int(d));
        }
    } else {
        // radar -> gt
        const int r = bid - 512;
        const int batch = r >> 4;
        const int g = r & 15;
        radar_pass(sm.r.tile, pc3, pc2 + batch * N_GT * 3, g_min3,
                   batch * N_RAD, g * RCHUNK);
    }
}

// ---------------- init ------------------------------------------------------
__global__ void init_kernel() {
    const int T1 = BATCH * N_UP;   // 32768
    const int T2 = BATCH * N_GT;   // 32768
    const int T3 = BATCH * N_RAD;  // 4096
    int i = blockIdx.x * blockDim.x + threadIdx.x;   // int4 index
    const int4 v = make_int4(0x7f7fffff, 0x7f7fffff, 0x7f7fffff, 0x7f7fffff);
    int n1 = T1 / 4, n2 = T2 / 4, n3 = T3 / 4;
    if (i < n1)                ((int4*)g_min1)[i] = v;
    else if (i < n1 + n2)      ((int4*)g_min2)[i - n1] = v;
    else if (i < n1 + n2 + n3) ((int4*)g_min3)[i - n1 - n2] = v;
}

// ---------------- final reduction (deterministic, vectorized) ---------------
__global__ void __launch_bounds__(1024)
reduce_kernel(const float* __restrict__ conf, float* __restrict__ out)
{
    int tid = threadIdx.x;
    float s_d1 = 0.f, s_sqrt1 = 0.f, s_d2 = 0.f, s_conf = 0.f;

    const int4* v1 = (const int4*)g_min1;              // 8192 int4
    for (int i = tid; i < (BATCH * N_UP) / 4; i += 1024) {
        int4 v = v1[i];
        float d0 = __int_as_float(v.x), d1 = __int_as_float(v.y);
        float d2 = __int_as_float(v.z), d3 = __int_as_float(v.w);
        s_d1 += (d0 + d1) + (d2 + d3);
        s_sqrt1 += (sqrtf(d0) + sqrtf(d1)) + (sqrtf(d2) + sqrtf(d3));
    }
    const int4* v2 = (const int4*)g_min2;
    for (int i = tid; i < (BATCH * N_GT) / 4; i += 1024) {
        int4 v = v2[i];
        s_d2 += (__int_as_float(v.x) + __int_as_float(v.y))
              + (__int_as_float(v.z) + __int_as_float(v.w));
    }
    const int4*   v3 = (const int4*)g_min3;            // 1024 int4
    const float4* c4 = (const float4*)conf;
    for (int i = tid; i < (BATCH * N_RAD) / 4; i += 1024) {
        int4 v = v3[i];
        float4 c = c4[i];
        float e0 = c.x - expf(-sqrtf(__int_as_float(v.x)));
        float e1 = c.y - expf(-sqrtf(__int_as_float(v.y)));
        float e2 = c.z - expf(-sqrtf(__int_as_float(v.z)));
        float e3 = c.w - expf(-sqrtf(__int_as_float(v.w)));
        s_conf += (e0 * e0 + e1 * e1) + (e2 * e2 + e3 * e3);
    }

    __shared__ float r1[1024], r2[1024], r3[1024], r4[1024];
    r1[tid] = s_d1; r2[tid] = s_sqrt1; r3[tid] = s_d2; r4[tid] = s_conf;
    __syncthreads();
    for (int s = 512; s > 0; s >>= 1) {
        if (tid < s) {
            r1[tid] += r1[tid + s];
            r2[tid] += r2[tid + s];
            r3[tid] += r3[tid + s];
            r4[tid] += r4[tid + s];
        }
        __syncthreads();
    }
    if (tid == 0) {
        const float inv_up  = 1.0f / (BATCH * N_UP);
        const float inv_gt  = 1.0f / (BATCH * N_GT);
        const float inv_rad = 1.0f / (BATCH * N_RAD);
        float mean1     = r1[0] * inv_up;
        float mean_sqrt = r2[0] * inv_up;
        float mean2     = r3[0] * inv_gt;
        float conf_loss = r4[0] * inv_rad;
        float chamfer = 0.5f * mean1 + 2.0f * mean2;
        out[0] = 0.5f * chamfer + 0.5f * conf_loss + mean_sqrt;  // ALPHA = 0.5
    }
}

extern "C" void kernel_launch(void* const* d_in, const int* in_sizes, int n_in,
                              void* d_out, int out_size)
{
    (void)in_sizes; (void)n_in; (void)out_size;
    const float* pc_up   = (const float*)d_in[0];
    // d_in[1] = pc_seed (unused by the reference loss)
    const float* pc_conf = (const float*)d_in[2];
    const float* pc2     = (const float*)d_in[3];
    const float* pc3     = (const float*)d_in[4];

    const int total_vec4 = (BATCH * (N_UP + N_GT + N_RAD)) / 4;  // 17408
    init_kernel<<<(total_vec4 + 255) / 256, 256>>>();
    pairs_kernel<<<576, NTHREADS>>>(pc_up, pc2, pc3);
    reduce_kernel<<<1, 1024>>>(pc_conf, (float*)d_out);
}